// round 9
// baseline (speedup 1.0000x reference)
#include <cuda_runtime.h>
#include <cuda_fp16.h>
#include <cstdint>
#include <cstddef>

#define NV      25000
#define NE      100000
#define NE_PAD  100096
#define NODE_IN 74
#define EDGE_IN 12
#define DOUT    64
#define EHID    128
#define NSTEPS  6

// Scratch (device globals; no runtime allocation allowed)
__device__ float  d_h[NV * DOUT];                     // node state
__device__ float  d_agg[NV * DOUT];                   // scatter accumulator
__device__ __half d_gh[NE_PAD * EHID];                // edge hidden (fp16), padded
__device__ __half d_We2t[DOUT * DOUT * EHID];         // We2^T [4096][128] fp16, 1 MB
__device__ __half d_ew[(size_t)NE * DOUT * DOUT];     // per-edge 64x64 fp16, 819 MB

// ---------------------------------------------------------------------------
__global__ void k_project(const float* __restrict__ nf,
                          const float* __restrict__ Wp,
                          const float* __restrict__ bp) {
    int v = blockIdx.x;
    int o = threadIdx.x;
    __shared__ float row[NODE_IN];
    for (int i = o; i < NODE_IN; i += DOUT) row[i] = nf[v * NODE_IN + i];
    __syncthreads();
    float acc = bp[o];
#pragma unroll
    for (int i = 0; i < NODE_IN; i++) acc += row[i] * Wp[i * DOUT + o];
    d_h[v * DOUT + o] = fmaxf(acc, 0.f);
}

// ---------------------------------------------------------------------------
__global__ void k_ehid(const float* __restrict__ ef,
                       const float* __restrict__ We1,
                       const float* __restrict__ be1) {
    int e = blockIdx.x;
    int k = threadIdx.x;
    __shared__ float row[EDGE_IN];
    if (k < EDGE_IN) row[k] = ef[e * EDGE_IN + k];
    __syncthreads();
    float acc = be1[k];
#pragma unroll
    for (int i = 0; i < EDGE_IN; i++) acc += row[i] * We1[i * EHID + k];
    d_gh[e * EHID + k] = __float2half(fmaxf(acc, 0.f));
}

// ---------------------------------------------------------------------------
__global__ void k_convW(const float* __restrict__ We2) {
    int idx = blockIdx.x * 256 + threadIdx.x;      // 524288 total
    int n = idx >> 7, k = idx & 127;
    d_We2t[idx] = __float2half(We2[k * 4096 + n]);
}

// ---------------------------------------------------------------------------
// ew = g @ We2 + be2. HMMA m16n8k16, ldmatrix feeds, 64x32 warp tiles
// (acc=64 regs -> 4 CTAs/SM, 16 warps). Block tile 128 edges x 64 cols.
// K = 4 chunks of 32, double-buffered cp.async. smem ~31 KB/CTA.
// ---------------------------------------------------------------------------
#define CH_STRIDE 40                       // halfs per row in chunk buffer (80B)

__device__ __forceinline__ void cp16(uint32_t smem_dst, const void* gmem_src) {
    asm volatile("cp.async.cg.shared.global [%0], [%1], 16;\n"
                 :: "r"(smem_dst), "l"(gmem_src));
}

__global__ __launch_bounds__(128, 4) void k_ew(const float* __restrict__ be2) {
    // [stage]: A = 128 rows x 40 halfs, then B = 64 rows x 40 halfs
    __shared__ __align__(16) __half sb[2][(128 + 64) * CH_STRIDE];
    __shared__ float be2s[64];

    int tid  = threadIdx.x;
    int warp = tid >> 5, lane = tid & 31;
    int g = lane >> 2, tig = lane & 3;
    int wm = (warp >> 1) * 64;             // warp edge offset   (0 / 64)
    int wn = (warp & 1) * 32;              // warp col offset    (0 / 32)
    int e0 = blockIdx.y * 128;
    int n0 = blockIdx.x * 64;

    if (tid < 64) be2s[tid] = be2[n0 + tid];

    // async chunk loader: K cols [32kc, 32kc+32) into stage st
    // chunk row = 32 halfs = 64 B = 4 x cp16.  A: 512 cp16, B: 256 cp16.
    auto load_chunk = [&](int kc, int st) {
#pragma unroll
        for (int it = 0; it < 4; it++) {   // A: 128 rows x 4
            int idx = tid + it * 128;
            int r = idx >> 2, j = idx & 3;
            cp16((uint32_t)__cvta_generic_to_shared(&sb[st][r * CH_STRIDE + 8 * j]),
                 &d_gh[(size_t)(e0 + r) * EHID + kc * 32 + 8 * j]);
        }
#pragma unroll
        for (int it = 0; it < 2; it++) {   // B: 64 rows x 4
            int idx = tid + it * 128;
            int r = idx >> 2, j = idx & 3;
            cp16((uint32_t)__cvta_generic_to_shared(
                     &sb[st][(128 + r) * CH_STRIDE + 8 * j]),
                 &d_We2t[(size_t)(n0 + r) * EHID + kc * 32 + 8 * j]);
        }
        asm volatile("cp.async.commit_group;\n");
    };

    load_chunk(0, 0);
    load_chunk(1, 1);

    // per-lane ldmatrix byte offsets within a stage buffer
    uint32_t offA[4], offB;
#pragma unroll
    for (int mt = 0; mt < 4; mt++)
        offA[mt] = (uint32_t)((wm + mt * 16 + (lane & 15)) * CH_STRIDE * 2 +
                              (lane >> 4) * 16);
    offB = (uint32_t)((128 + wn + ((lane >> 4) << 3) + (lane & 7)) * CH_STRIDE * 2 +
                      ((lane >> 3) & 1) * 16);

    float acc[4][4][4];
#pragma unroll
    for (int mt = 0; mt < 4; mt++)
#pragma unroll
        for (int nt = 0; nt < 4; nt++)
            acc[mt][nt][0] = acc[mt][nt][1] = acc[mt][nt][2] = acc[mt][nt][3] = 0.f;

#pragma unroll
    for (int kc = 0; kc < 4; kc++) {
        if (kc < 3) asm volatile("cp.async.wait_group 1;\n");
        else        asm volatile("cp.async.wait_group 0;\n");
        __syncthreads();

        int st = kc & 1;
        uint32_t base = (uint32_t)__cvta_generic_to_shared(&sb[st][0]);

#pragma unroll
        for (int kk = 0; kk < 2; kk++) {
            unsigned a[4][4];
#pragma unroll
            for (int mt = 0; mt < 4; mt++)
                asm volatile("ldmatrix.sync.aligned.m8n8.x4.shared.b16 {%0,%1,%2,%3}, [%4];"
                             : "=r"(a[mt][0]), "=r"(a[mt][1]), "=r"(a[mt][2]), "=r"(a[mt][3])
                             : "r"(base + offA[mt] + kk * 32));
#pragma unroll
            for (int ntt = 0; ntt < 2; ntt++) {
                unsigned b0, b1, b2, b3;
                asm volatile("ldmatrix.sync.aligned.m8n8.x4.shared.b16 {%0,%1,%2,%3}, [%4];"
                             : "=r"(b0), "=r"(b1), "=r"(b2), "=r"(b3)
                             : "r"(base + offB + ntt * 16 * CH_STRIDE * 2 + kk * 32));
#pragma unroll
                for (int mt = 0; mt < 4; mt++) {
                    asm volatile(
                        "mma.sync.aligned.m16n8k16.row.col.f32.f16.f16.f32 "
                        "{%0,%1,%2,%3}, {%4,%5,%6,%7}, {%8,%9}, {%0,%1,%2,%3};"
                        : "+f"(acc[mt][2*ntt][0]), "+f"(acc[mt][2*ntt][1]),
                          "+f"(acc[mt][2*ntt][2]), "+f"(acc[mt][2*ntt][3])
                        : "r"(a[mt][0]), "r"(a[mt][1]), "r"(a[mt][2]), "r"(a[mt][3]),
                          "r"(b0), "r"(b1));
                    asm volatile(
                        "mma.sync.aligned.m16n8k16.row.col.f32.f16.f16.f32 "
                        "{%0,%1,%2,%3}, {%4,%5,%6,%7}, {%8,%9}, {%0,%1,%2,%3};"
                        : "+f"(acc[mt][2*ntt+1][0]), "+f"(acc[mt][2*ntt+1][1]),
                          "+f"(acc[mt][2*ntt+1][2]), "+f"(acc[mt][2*ntt+1][3])
                        : "r"(a[mt][0]), "r"(a[mt][1]), "r"(a[mt][2]), "r"(a[mt][3]),
                          "r"(b2), "r"(b3));
                }
            }
        }
        __syncthreads();
        if (kc < 2) load_chunk(kc + 2, st);
    }

    // epilogue: stage through smem for coalesced 16B stores (128 x 64 tile)
    __half(*Outs)[72] = reinterpret_cast<__half(*)[72]>(&sb[0][0]);   // 128x72 halfs
#pragma unroll
    for (int mt = 0; mt < 4; mt++)
#pragma unroll
        for (int nt = 0; nt < 4; nt++) {
            int r = wm + mt * 16 + g;
            int c = wn + nt * 8 + 2 * tig;
            __half2 v0 = __floats2half2_rn(acc[mt][nt][0] + be2s[c],
                                           acc[mt][nt][1] + be2s[c + 1]);
            __half2 v1 = __floats2half2_rn(acc[mt][nt][2] + be2s[c],
                                           acc[mt][nt][3] + be2s[c + 1]);
            *(__half2*)&Outs[r][c]     = v0;
            *(__half2*)&Outs[r + 8][c] = v1;
        }
    __syncthreads();

    for (int idx = tid; idx < 128 * 8; idx += 128) {
        int e = idx >> 3, j = idx & 7;
        if (e0 + e < NE)
            *(uint4*)&d_ew[(size_t)(e0 + e) * 4096 + n0 + 8 * j] =
                *(uint4*)&Outs[e][8 * j];
    }
}

// ---------------------------------------------------------------------------
// msg[e] = h[src[e]] @ ew[e]; warp-uniform skip of exact-zero h rows (ReLU
// sparsity) -> whole 128B ew row reads skipped, bit-identical math.
// ---------------------------------------------------------------------------
__global__ void k_msg(const int* __restrict__ src,
                      const int* __restrict__ dst) {
    int t  = threadIdx.x;
    int ty = threadIdx.y;
    int e  = blockIdx.x * 8 + ty;
    __shared__ float hs[8][64];
    int s = src[e];
    hs[ty][t]      = d_h[s * 64 + t];
    hs[ty][t + 32] = d_h[s * 64 + t + 32];
    __syncwarp();

    const __half* ewp = d_ew + (size_t)e * 4096 + 2 * t;
    float ax = 0.f, ay = 0.f;
#pragma unroll 8
    for (int i = 0; i < 64; i++) {
        float hv = hs[ty][i];
        if (hv > 0.f) {
            __half2 w = *(const __half2*)(ewp + i * 64);
            float2 wf = __half22float2(w);
            ax += hv * wf.x;
            ay += hv * wf.y;
        }
    }
    int dv = dst[e];
    atomicAdd(&d_agg[dv * 64 + 2 * t],     ax);
    atomicAdd(&d_agg[dv * 64 + 2 * t + 1], ay);
}

// ---------------------------------------------------------------------------
__global__ void k_zero() {
    int i = blockIdx.x * blockDim.x + threadIdx.x;
    if (i < NV * DOUT) d_agg[i] = 0.f;
}

// relu + writeback, re-zero d_agg for the next step (fuses k_zero)
__global__ void k_relu(const float* __restrict__ bias, float* __restrict__ out) {
    int i = blockIdx.x * blockDim.x + threadIdx.x;
    if (i < NV * DOUT) {
        float v = fmaxf(d_agg[i] + bias[i & (DOUT - 1)], 0.f);
        d_agg[i] = 0.f;
        d_h[i] = v;
        if (out) out[i] = v;
    }
}

// ---------------------------------------------------------------------------
extern "C" void kernel_launch(void* const* d_in, const int* in_sizes, int n_in,
                              void* d_out, int out_size) {
    const float* nf   = (const float*)d_in[0];
    const float* ef   = (const float*)d_in[1];
    const int*   src  = (const int*)  d_in[2];
    const int*   dst  = (const int*)  d_in[3];
    const float* Wp   = (const float*)d_in[4];
    const float* bp   = (const float*)d_in[5];
    const float* We1  = (const float*)d_in[6];
    const float* be1  = (const float*)d_in[7];
    const float* We2  = (const float*)d_in[8];
    const float* be2  = (const float*)d_in[9];
    const float* bias = (const float*)d_in[10];
    float* out = (float*)d_out;

    k_project<<<NV, DOUT>>>(nf, Wp, bp);
    k_ehid<<<NE, EHID>>>(ef, We1, be1);
    k_convW<<<(DOUT * DOUT * EHID) / 256, 256>>>(We2);
    k_ew<<<dim3(64, 782), 128>>>(be2);

    k_zero<<<(NV * DOUT) / 256, 256>>>();
    for (int s = 0; s < NSTEPS; s++) {
        k_msg<<<NE / 8, dim3(32, 8)>>>(src, dst);
        k_relu<<<(NV * DOUT) / 256, 256>>>(bias, (s == NSTEPS - 1) ? out : nullptr);
    }
}

// round 10
// speedup vs baseline: 1.0920x; 1.0920x over previous
#include <cuda_runtime.h>
#include <cuda_fp16.h>
#include <cstdint>
#include <cstddef>

#define NV      25000
#define NE      100000
#define NE_PAD  100096
#define NODE_IN 74
#define EDGE_IN 12
#define DOUT    64
#define EHID    128
#define NSTEPS  6

// Scratch (device globals; no runtime allocation allowed)
__device__ float  d_h[NV * DOUT];                     // node state
__device__ float  d_agg[NV * DOUT];                   // scatter accumulator
__device__ __half d_gh[NE_PAD * EHID];                // edge hidden (fp16), padded
__device__ __half d_We2t[DOUT * DOUT * EHID];         // We2^T [4096][128] fp16, 1 MB
__device__ __half d_ew[(size_t)NE * DOUT * DOUT];     // per-edge 64x64 fp16, 819 MB

// ---------------------------------------------------------------------------
__global__ void k_project(const float* __restrict__ nf,
                          const float* __restrict__ Wp,
                          const float* __restrict__ bp) {
    int v = blockIdx.x;
    int o = threadIdx.x;
    __shared__ float row[NODE_IN];
    for (int i = o; i < NODE_IN; i += DOUT) row[i] = nf[v * NODE_IN + i];
    __syncthreads();
    float acc = bp[o];
#pragma unroll
    for (int i = 0; i < NODE_IN; i++) acc += row[i] * Wp[i * DOUT + o];
    d_h[v * DOUT + o] = fmaxf(acc, 0.f);
}

// ---------------------------------------------------------------------------
__global__ void k_ehid(const float* __restrict__ ef,
                       const float* __restrict__ We1,
                       const float* __restrict__ be1) {
    int e = blockIdx.x;
    int k = threadIdx.x;
    __shared__ float row[EDGE_IN];
    if (k < EDGE_IN) row[k] = ef[e * EDGE_IN + k];
    __syncthreads();
    float acc = be1[k];
#pragma unroll
    for (int i = 0; i < EDGE_IN; i++) acc += row[i] * We1[i * EHID + k];
    d_gh[e * EHID + k] = __float2half(fmaxf(acc, 0.f));
}

// ---------------------------------------------------------------------------
__global__ void k_convW(const float* __restrict__ We2) {
    int idx = blockIdx.x * 256 + threadIdx.x;      // 524288 total
    int n = idx >> 7, k = idx & 127;
    d_We2t[idx] = __float2half(We2[k * 4096 + n]);
}

// ---------------------------------------------------------------------------
// ew = g @ We2 + be2. HMMA m16n8k16, ldmatrix feeds, 64x64 warp tiles.
// Block tile 128 edges x 128 cols. K = 4 chunks of 32, double-buffered
// with cp.async (R7 configuration: best measured, 414 us).
// ---------------------------------------------------------------------------
#define CH_STRIDE 40                       // halfs per row in chunk buffer (80B)

__device__ __forceinline__ void cp16(uint32_t smem_dst, const void* gmem_src) {
    asm volatile("cp.async.cg.shared.global [%0], [%1], 16;\n"
                 :: "r"(smem_dst), "l"(gmem_src));
}

__global__ __launch_bounds__(128, 3) void k_ew(const float* __restrict__ be2) {
    // [stage][A=0/B=1][128 rows x 40 halfs]
    __shared__ __align__(16) __half sb[2][2][128 * CH_STRIDE];
    __shared__ float be2s[128];

    int tid  = threadIdx.x;
    int warp = tid >> 5, lane = tid & 31;
    int g = lane >> 2, tig = lane & 3;
    int wm = (warp >> 1) * 64;             // warp edge offset
    int wn = (warp & 1) * 64;              // warp col offset
    int e0 = blockIdx.y * 128;
    int n0 = blockIdx.x * 128;

    be2s[tid] = be2[n0 + tid];

    // async chunk loader: K cols [32kc, 32kc+32) into stage st
    auto load_chunk = [&](int kc, int st) {
#pragma unroll
        for (int it = 0; it < 4; it++) {
            int idx = tid + it * 128;              // 0..511
            int r = idx >> 2, j = idx & 3;
            cp16((uint32_t)__cvta_generic_to_shared(&sb[st][0][r * CH_STRIDE + 8 * j]),
                 &d_gh[(size_t)(e0 + r) * EHID + kc * 32 + 8 * j]);
            cp16((uint32_t)__cvta_generic_to_shared(&sb[st][1][r * CH_STRIDE + 8 * j]),
                 &d_We2t[(size_t)(n0 + r) * EHID + kc * 32 + 8 * j]);
        }
        asm volatile("cp.async.commit_group;\n");
    };

    load_chunk(0, 0);
    load_chunk(1, 1);

    uint32_t offA[4], offB[4];
#pragma unroll
    for (int mt = 0; mt < 4; mt++)
        offA[mt] = (uint32_t)((wm + mt * 16 + (lane & 15)) * CH_STRIDE * 2 +
                              (lane >> 4) * 16);
#pragma unroll
    for (int ntt = 0; ntt < 4; ntt++)
        offB[ntt] = (uint32_t)((wn + ntt * 16 + ((lane >> 4) << 3) + (lane & 7)) *
                               CH_STRIDE * 2 + ((lane >> 3) & 1) * 16);

    float acc[4][8][4];
#pragma unroll
    for (int mt = 0; mt < 4; mt++)
#pragma unroll
        for (int nt = 0; nt < 8; nt++)
            acc[mt][nt][0] = acc[mt][nt][1] = acc[mt][nt][2] = acc[mt][nt][3] = 0.f;

#pragma unroll
    for (int kc = 0; kc < 4; kc++) {
        if (kc < 3) asm volatile("cp.async.wait_group 1;\n");
        else        asm volatile("cp.async.wait_group 0;\n");
        __syncthreads();

        int st = kc & 1;
        uint32_t baseA = (uint32_t)__cvta_generic_to_shared(&sb[st][0][0]);
        uint32_t baseB = (uint32_t)__cvta_generic_to_shared(&sb[st][1][0]);

#pragma unroll
        for (int kk = 0; kk < 2; kk++) {
            unsigned a[4][4];
#pragma unroll
            for (int mt = 0; mt < 4; mt++)
                asm volatile("ldmatrix.sync.aligned.m8n8.x4.shared.b16 {%0,%1,%2,%3}, [%4];"
                             : "=r"(a[mt][0]), "=r"(a[mt][1]), "=r"(a[mt][2]), "=r"(a[mt][3])
                             : "r"(baseA + offA[mt] + kk * 32));
#pragma unroll
            for (int ntt = 0; ntt < 4; ntt++) {
                unsigned b0, b1, b2, b3;
                asm volatile("ldmatrix.sync.aligned.m8n8.x4.shared.b16 {%0,%1,%2,%3}, [%4];"
                             : "=r"(b0), "=r"(b1), "=r"(b2), "=r"(b3)
                             : "r"(baseB + offB[ntt] + kk * 32));
#pragma unroll
                for (int mt = 0; mt < 4; mt++) {
                    asm volatile(
                        "mma.sync.aligned.m16n8k16.row.col.f32.f16.f16.f32 "
                        "{%0,%1,%2,%3}, {%4,%5,%6,%7}, {%8,%9}, {%0,%1,%2,%3};"
                        : "+f"(acc[mt][2*ntt][0]), "+f"(acc[mt][2*ntt][1]),
                          "+f"(acc[mt][2*ntt][2]), "+f"(acc[mt][2*ntt][3])
                        : "r"(a[mt][0]), "r"(a[mt][1]), "r"(a[mt][2]), "r"(a[mt][3]),
                          "r"(b0), "r"(b1));
                    asm volatile(
                        "mma.sync.aligned.m16n8k16.row.col.f32.f16.f16.f32 "
                        "{%0,%1,%2,%3}, {%4,%5,%6,%7}, {%8,%9}, {%0,%1,%2,%3};"
                        : "+f"(acc[mt][2*ntt+1][0]), "+f"(acc[mt][2*ntt+1][1]),
                          "+f"(acc[mt][2*ntt+1][2]), "+f"(acc[mt][2*ntt+1][3])
                        : "r"(a[mt][0]), "r"(a[mt][1]), "r"(a[mt][2]), "r"(a[mt][3]),
                          "r"(b2), "r"(b3));
                }
            }
        }
        __syncthreads();
        if (kc < 2) load_chunk(kc + 2, st);
    }

    // epilogue: stage through smem for coalesced 16B stores
    __half(*Outs)[136] = reinterpret_cast<__half(*)[136]>(&sb[0][0][0]);  // 128x136
#pragma unroll
    for (int mt = 0; mt < 4; mt++)
#pragma unroll
        for (int nt = 0; nt < 8; nt++) {
            int r = wm + mt * 16 + g;
            int c = wn + nt * 8 + 2 * tig;
            __half2 v0 = __floats2half2_rn(acc[mt][nt][0] + be2s[c],
                                           acc[mt][nt][1] + be2s[c + 1]);
            __half2 v1 = __floats2half2_rn(acc[mt][nt][2] + be2s[c],
                                           acc[mt][nt][3] + be2s[c + 1]);
            *(__half2*)&Outs[r][c]     = v0;
            *(__half2*)&Outs[r + 8][c] = v1;
        }
    __syncthreads();

    for (int idx = tid; idx < 128 * 16; idx += 128) {
        int e = idx >> 4, j = idx & 15;
        if (e0 + e < NE)
            *(uint4*)&d_ew[(size_t)(e0 + e) * 4096 + n0 + 8 * j] =
                *(uint4*)&Outs[e][8 * j];
    }
}

// ---------------------------------------------------------------------------
// msg[e] = h[src[e]] @ ew[e]. ReLU sparsity handled by warp compaction:
// ballot + prefix-popc builds a dense (idx,val) list of nonzero h entries,
// then a BRANCH-FREE loop over nnz entries (unroll 4 -> high MLP).
// Skipped terms are exact +0.0 and remaining order is ascending-i, so the
// result is bit-identical to the dense loop.
// ---------------------------------------------------------------------------
__global__ void k_msg(const int* __restrict__ src,
                      const int* __restrict__ dst) {
    int t  = threadIdx.x;
    int ty = threadIdx.y;
    int e  = blockIdx.x * 8 + ty;
    __shared__ float sval[8][64];
    __shared__ int   sidx[8][64];

    int s = src[e];
    float h0 = d_h[s * 64 + t];
    float h1 = d_h[s * 64 + 32 + t];
    unsigned m0 = __ballot_sync(0xffffffffu, h0 > 0.f);
    unsigned m1 = __ballot_sync(0xffffffffu, h1 > 0.f);
    int c0 = __popc(m0);
    if (h0 > 0.f) {
        int p = __popc(m0 & ((1u << t) - 1u));
        sval[ty][p] = h0; sidx[ty][p] = t;
    }
    if (h1 > 0.f) {
        int p = c0 + __popc(m1 & ((1u << t) - 1u));
        sval[ty][p] = h1; sidx[ty][p] = t + 32;
    }
    int nnz = c0 + __popc(m1);
    __syncwarp();

    const __half* ewp = d_ew + (size_t)e * 4096 + 2 * t;
    float ax = 0.f, ay = 0.f;
    int p = 0;
    for (; p + 4 <= nnz; p += 4) {
#pragma unroll
        for (int u = 0; u < 4; u++) {
            int   i  = sidx[ty][p + u];              // broadcast LDS
            float hv = sval[ty][p + u];
            __half2 w = *(const __half2*)(ewp + i * 64);
            float2 wf = __half22float2(w);
            ax += hv * wf.x;
            ay += hv * wf.y;
        }
    }
    for (; p < nnz; p++) {
        int   i  = sidx[ty][p];
        float hv = sval[ty][p];
        __half2 w = *(const __half2*)(ewp + i * 64);
        float2 wf = __half22float2(w);
        ax += hv * wf.x;
        ay += hv * wf.y;
    }
    int dv = dst[e];
    atomicAdd(&d_agg[dv * 64 + 2 * t],     ax);
    atomicAdd(&d_agg[dv * 64 + 2 * t + 1], ay);
}

// ---------------------------------------------------------------------------
__global__ void k_zero() {
    int i = blockIdx.x * blockDim.x + threadIdx.x;
    if (i < NV * DOUT) d_agg[i] = 0.f;
}

// relu + writeback, re-zero d_agg for the next step (fuses k_zero)
__global__ void k_relu(const float* __restrict__ bias, float* __restrict__ out) {
    int i = blockIdx.x * blockDim.x + threadIdx.x;
    if (i < NV * DOUT) {
        float v = fmaxf(d_agg[i] + bias[i & (DOUT - 1)], 0.f);
        d_agg[i] = 0.f;
        d_h[i] = v;
        if (out) out[i] = v;
    }
}

// ---------------------------------------------------------------------------
extern "C" void kernel_launch(void* const* d_in, const int* in_sizes, int n_in,
                              void* d_out, int out_size) {
    const float* nf   = (const float*)d_in[0];
    const float* ef   = (const float*)d_in[1];
    const int*   src  = (const int*)  d_in[2];
    const int*   dst  = (const int*)  d_in[3];
    const float* Wp   = (const float*)d_in[4];
    const float* bp   = (const float*)d_in[5];
    const float* We1  = (const float*)d_in[6];
    const float* be1  = (const float*)d_in[7];
    const float* We2  = (const float*)d_in[8];
    const float* be2  = (const float*)d_in[9];
    const float* bias = (const float*)d_in[10];
    float* out = (float*)d_out;

    k_project<<<NV, DOUT>>>(nf, Wp, bp);
    k_ehid<<<NE, EHID>>>(ef, We1, be1);
    k_convW<<<(DOUT * DOUT * EHID) / 256, 256>>>(We2);
    k_ew<<<dim3(32, 782), 128>>>(be2);

    k_zero<<<(NV * DOUT) / 256, 256>>>();
    for (int s = 0; s < NSTEPS; s++) {
        k_msg<<<NE / 8, dim3(32, 8)>>>(src, dst);
        k_relu<<<(NV * DOUT) / 256, 256>>>(bias, (s == NSTEPS - 1) ? out : nullptr);
    }
}

// round 11
// speedup vs baseline: 1.2304x; 1.1268x over previous
#include <cuda_runtime.h>
#include <cuda_fp16.h>
#include <cstdint>
#include <cstddef>

#define NV      25000
#define NE      100000
#define NE_PAD  100096
#define NODE_IN 74
#define EDGE_IN 12
#define DOUT    64
#define EHID    128
#define NSTEPS  6

// Scratch (device globals; no runtime allocation allowed)
__device__ float  d_h[NV * DOUT];                     // node state
__device__ float  d_agg[NV * DOUT];                   // scatter accumulator
__device__ __half d_gh[NE_PAD * EHID];                // edge hidden (fp16), padded
__device__ __half d_We2t[DOUT * DOUT * EHID];         // We2^T [4096][128] fp16, 1 MB
__device__ __half d_ew[(size_t)NE * DOUT * DOUT];     // per-edge 64x64 fp16, 819 MB

// ---------------------------------------------------------------------------
__global__ void k_project(const float* __restrict__ nf,
                          const float* __restrict__ Wp,
                          const float* __restrict__ bp) {
    int v = blockIdx.x;
    int o = threadIdx.x;
    __shared__ float row[NODE_IN];
    for (int i = o; i < NODE_IN; i += DOUT) row[i] = nf[v * NODE_IN + i];
    __syncthreads();
    float acc = bp[o];
#pragma unroll
    for (int i = 0; i < NODE_IN; i++) acc += row[i] * Wp[i * DOUT + o];
    d_h[v * DOUT + o] = fmaxf(acc, 0.f);
}

// ---------------------------------------------------------------------------
__global__ void k_ehid(const float* __restrict__ ef,
                       const float* __restrict__ We1,
                       const float* __restrict__ be1) {
    int e = blockIdx.x;
    int k = threadIdx.x;
    __shared__ float row[EDGE_IN];
    if (k < EDGE_IN) row[k] = ef[e * EDGE_IN + k];
    __syncthreads();
    float acc = be1[k];
#pragma unroll
    for (int i = 0; i < EDGE_IN; i++) acc += row[i] * We1[i * EHID + k];
    d_gh[e * EHID + k] = __float2half(fmaxf(acc, 0.f));
}

// ---------------------------------------------------------------------------
__global__ void k_convW(const float* __restrict__ We2) {
    int idx = blockIdx.x * 256 + threadIdx.x;      // 524288 total
    int n = idx >> 7, k = idx & 127;
    d_We2t[idx] = __float2half(We2[k * 4096 + n]);
}

// ---------------------------------------------------------------------------
// ew = g @ We2 + be2. HMMA m16n8k16, ldmatrix feeds, 64x64 warp tiles.
// Block tile 128 edges x 128 cols. K = 4 chunks of 32, double-buffered
// with cp.async (best measured configuration, ~412 us). FROZEN.
// ---------------------------------------------------------------------------
#define CH_STRIDE 40                       // halfs per row in chunk buffer (80B)

__device__ __forceinline__ void cp16(uint32_t smem_dst, const void* gmem_src) {
    asm volatile("cp.async.cg.shared.global [%0], [%1], 16;\n"
                 :: "r"(smem_dst), "l"(gmem_src));
}

__global__ __launch_bounds__(128, 3) void k_ew(const float* __restrict__ be2) {
    // [stage][A=0/B=1][128 rows x 40 halfs]
    __shared__ __align__(16) __half sb[2][2][128 * CH_STRIDE];
    __shared__ float be2s[128];

    int tid  = threadIdx.x;
    int warp = tid >> 5, lane = tid & 31;
    int g = lane >> 2, tig = lane & 3;
    int wm = (warp >> 1) * 64;             // warp edge offset
    int wn = (warp & 1) * 64;              // warp col offset
    int e0 = blockIdx.y * 128;
    int n0 = blockIdx.x * 128;

    be2s[tid] = be2[n0 + tid];

    // async chunk loader: K cols [32kc, 32kc+32) into stage st
    auto load_chunk = [&](int kc, int st) {
#pragma unroll
        for (int it = 0; it < 4; it++) {
            int idx = tid + it * 128;              // 0..511
            int r = idx >> 2, j = idx & 3;
            cp16((uint32_t)__cvta_generic_to_shared(&sb[st][0][r * CH_STRIDE + 8 * j]),
                 &d_gh[(size_t)(e0 + r) * EHID + kc * 32 + 8 * j]);
            cp16((uint32_t)__cvta_generic_to_shared(&sb[st][1][r * CH_STRIDE + 8 * j]),
                 &d_We2t[(size_t)(n0 + r) * EHID + kc * 32 + 8 * j]);
        }
        asm volatile("cp.async.commit_group;\n");
    };

    load_chunk(0, 0);
    load_chunk(1, 1);

    uint32_t offA[4], offB[4];
#pragma unroll
    for (int mt = 0; mt < 4; mt++)
        offA[mt] = (uint32_t)((wm + mt * 16 + (lane & 15)) * CH_STRIDE * 2 +
                              (lane >> 4) * 16);
#pragma unroll
    for (int ntt = 0; ntt < 4; ntt++)
        offB[ntt] = (uint32_t)((wn + ntt * 16 + ((lane >> 4) << 3) + (lane & 7)) *
                               CH_STRIDE * 2 + ((lane >> 3) & 1) * 16);

    float acc[4][8][4];
#pragma unroll
    for (int mt = 0; mt < 4; mt++)
#pragma unroll
        for (int nt = 0; nt < 8; nt++)
            acc[mt][nt][0] = acc[mt][nt][1] = acc[mt][nt][2] = acc[mt][nt][3] = 0.f;

#pragma unroll
    for (int kc = 0; kc < 4; kc++) {
        if (kc < 3) asm volatile("cp.async.wait_group 1;\n");
        else        asm volatile("cp.async.wait_group 0;\n");
        __syncthreads();

        int st = kc & 1;
        uint32_t baseA = (uint32_t)__cvta_generic_to_shared(&sb[st][0][0]);
        uint32_t baseB = (uint32_t)__cvta_generic_to_shared(&sb[st][1][0]);

#pragma unroll
        for (int kk = 0; kk < 2; kk++) {
            unsigned a[4][4];
#pragma unroll
            for (int mt = 0; mt < 4; mt++)
                asm volatile("ldmatrix.sync.aligned.m8n8.x4.shared.b16 {%0,%1,%2,%3}, [%4];"
                             : "=r"(a[mt][0]), "=r"(a[mt][1]), "=r"(a[mt][2]), "=r"(a[mt][3])
                             : "r"(baseA + offA[mt] + kk * 32));
#pragma unroll
            for (int ntt = 0; ntt < 4; ntt++) {
                unsigned b0, b1, b2, b3;
                asm volatile("ldmatrix.sync.aligned.m8n8.x4.shared.b16 {%0,%1,%2,%3}, [%4];"
                             : "=r"(b0), "=r"(b1), "=r"(b2), "=r"(b3)
                             : "r"(baseB + offB[ntt] + kk * 32));
#pragma unroll
                for (int mt = 0; mt < 4; mt++) {
                    asm volatile(
                        "mma.sync.aligned.m16n8k16.row.col.f32.f16.f16.f32 "
                        "{%0,%1,%2,%3}, {%4,%5,%6,%7}, {%8,%9}, {%0,%1,%2,%3};"
                        : "+f"(acc[mt][2*ntt][0]), "+f"(acc[mt][2*ntt][1]),
                          "+f"(acc[mt][2*ntt][2]), "+f"(acc[mt][2*ntt][3])
                        : "r"(a[mt][0]), "r"(a[mt][1]), "r"(a[mt][2]), "r"(a[mt][3]),
                          "r"(b0), "r"(b1));
                    asm volatile(
                        "mma.sync.aligned.m16n8k16.row.col.f32.f16.f16.f32 "
                        "{%0,%1,%2,%3}, {%4,%5,%6,%7}, {%8,%9}, {%0,%1,%2,%3};"
                        : "+f"(acc[mt][2*ntt+1][0]), "+f"(acc[mt][2*ntt+1][1]),
                          "+f"(acc[mt][2*ntt+1][2]), "+f"(acc[mt][2*ntt+1][3])
                        : "r"(a[mt][0]), "r"(a[mt][1]), "r"(a[mt][2]), "r"(a[mt][3]),
                          "r"(b2), "r"(b3));
                }
            }
        }
        __syncthreads();
        if (kc < 2) load_chunk(kc + 2, st);
    }

    // epilogue: stage through smem for coalesced 16B stores
    __half(*Outs)[136] = reinterpret_cast<__half(*)[136]>(&sb[0][0][0]);  // 128x136
#pragma unroll
    for (int mt = 0; mt < 4; mt++)
#pragma unroll
        for (int nt = 0; nt < 8; nt++) {
            int r = wm + mt * 16 + g;
            int c = wn + nt * 8 + 2 * tig;
            __half2 v0 = __floats2half2_rn(acc[mt][nt][0] + be2s[c],
                                           acc[mt][nt][1] + be2s[c + 1]);
            __half2 v1 = __floats2half2_rn(acc[mt][nt][2] + be2s[c],
                                           acc[mt][nt][3] + be2s[c + 1]);
            *(__half2*)&Outs[r][c]     = v0;
            *(__half2*)&Outs[r + 8][c] = v1;
        }
    __syncthreads();

    for (int idx = tid; idx < 128 * 16; idx += 128) {
        int e = idx >> 4, j = idx & 15;
        if (e0 + e < NE)
            *(uint4*)&d_ew[(size_t)(e0 + e) * 4096 + n0 + 8 * j] =
                *(uint4*)&Outs[e][8 * j];
    }
}

// ---------------------------------------------------------------------------
// msg[e] = h[src[e]] @ ew[e]. Warp compaction of nonzero h entries, then a
// branch-free loop. Unroll 8 with explicit idx/val gather -> LDG batch of 8
// (MLP ~8). Bit-identical to the dense loop (skipped terms are exact +0.0,
// ascending-i order preserved).
// ---------------------------------------------------------------------------
__global__ void k_msg(const int* __restrict__ src,
                      const int* __restrict__ dst) {
    int t  = threadIdx.x;
    int ty = threadIdx.y;
    int e  = blockIdx.x * 8 + ty;
    __shared__ float sval[8][64];
    __shared__ int   sidx[8][64];

    int s = src[e];
    float h0 = d_h[s * 64 + t];
    float h1 = d_h[s * 64 + 32 + t];
    unsigned m0 = __ballot_sync(0xffffffffu, h0 > 0.f);
    unsigned m1 = __ballot_sync(0xffffffffu, h1 > 0.f);
    int c0 = __popc(m0);
    if (h0 > 0.f) {
        int p = __popc(m0 & ((1u << t) - 1u));
        sval[ty][p] = h0; sidx[ty][p] = t;
    }
    if (h1 > 0.f) {
        int p = c0 + __popc(m1 & ((1u << t) - 1u));
        sval[ty][p] = h1; sidx[ty][p] = t + 32;
    }
    int nnz = c0 + __popc(m1);
    __syncwarp();

    const __half* ewp = d_ew + (size_t)e * 4096 + 2 * t;
    float ax = 0.f, ay = 0.f;
    int p = 0;
    for (; p + 8 <= nnz; p += 8) {
        int   iv[8];
        float hv[8];
        __half2 w[8];
#pragma unroll
        for (int u = 0; u < 8; u++) { iv[u] = sidx[ty][p + u]; hv[u] = sval[ty][p + u]; }
#pragma unroll
        for (int u = 0; u < 8; u++) w[u] = *(const __half2*)(ewp + iv[u] * 64);
#pragma unroll
        for (int u = 0; u < 8; u++) {
            float2 wf = __half22float2(w[u]);
            ax += hv[u] * wf.x;
            ay += hv[u] * wf.y;
        }
    }
    for (; p + 4 <= nnz; p += 4) {
        int   iv[4];
        float hv[4];
        __half2 w[4];
#pragma unroll
        for (int u = 0; u < 4; u++) { iv[u] = sidx[ty][p + u]; hv[u] = sval[ty][p + u]; }
#pragma unroll
        for (int u = 0; u < 4; u++) w[u] = *(const __half2*)(ewp + iv[u] * 64);
#pragma unroll
        for (int u = 0; u < 4; u++) {
            float2 wf = __half22float2(w[u]);
            ax += hv[u] * wf.x;
            ay += hv[u] * wf.y;
        }
    }
    for (; p < nnz; p++) {
        int   i  = sidx[ty][p];
        float hv = sval[ty][p];
        __half2 w = *(const __half2*)(ewp + i * 64);
        float2 wf = __half22float2(w);
        ax += hv * wf.x;
        ay += hv * wf.y;
    }
    int dv = dst[e];
    atomicAdd(&d_agg[dv * 64 + 2 * t],     ax);
    atomicAdd(&d_agg[dv * 64 + 2 * t + 1], ay);
}

// ---------------------------------------------------------------------------
__global__ void k_zero() {
    int i = blockIdx.x * blockDim.x + threadIdx.x;
    if (i < NV * DOUT) d_agg[i] = 0.f;
}

// relu + writeback + re-zero d_agg, vectorized float4
__global__ void k_relu(const float* __restrict__ bias, float* __restrict__ out) {
    int idx = blockIdx.x * blockDim.x + threadIdx.x;
    int i = idx * 4;
    if (i < NV * DOUT) {
        float4 a = *(float4*)&d_agg[i];
        float4 b = *(const float4*)&bias[i & (DOUT - 1)];
        float4 v;
        v.x = fmaxf(a.x + b.x, 0.f);
        v.y = fmaxf(a.y + b.y, 0.f);
        v.z = fmaxf(a.z + b.z, 0.f);
        v.w = fmaxf(a.w + b.w, 0.f);
        *(float4*)&d_agg[i] = make_float4(0.f, 0.f, 0.f, 0.f);
        *(float4*)&d_h[i] = v;
        if (out) *(float4*)&out[i] = v;
    }
}

// ---------------------------------------------------------------------------
extern "C" void kernel_launch(void* const* d_in, const int* in_sizes, int n_in,
                              void* d_out, int out_size) {
    const float* nf   = (const float*)d_in[0];
    const float* ef   = (const float*)d_in[1];
    const int*   src  = (const int*)  d_in[2];
    const int*   dst  = (const int*)  d_in[3];
    const float* Wp   = (const float*)d_in[4];
    const float* bp   = (const float*)d_in[5];
    const float* We1  = (const float*)d_in[6];
    const float* be1  = (const float*)d_in[7];
    const float* We2  = (const float*)d_in[8];
    const float* be2  = (const float*)d_in[9];
    const float* bias = (const float*)d_in[10];
    float* out = (float*)d_out;

    k_project<<<NV, DOUT>>>(nf, Wp, bp);
    k_ehid<<<NE, EHID>>>(ef, We1, be1);
    k_convW<<<(DOUT * DOUT * EHID) / 256, 256>>>(We2);
    k_ew<<<dim3(32, 782), 128>>>(be2);

    k_zero<<<(NV * DOUT) / 256, 256>>>();
    for (int s = 0; s < NSTEPS; s++) {
        k_msg<<<NE / 8, dim3(32, 8)>>>(src, dst);
        k_relu<<<(NV * DOUT / 4 + 255) / 256, 256>>>(bias, (s == NSTEPS - 1) ? out : nullptr);
    }
}

// round 13
// speedup vs baseline: 1.3505x; 1.0975x over previous
#include <cuda_runtime.h>
#include <cuda_fp16.h>
#include <cstdint>
#include <cstddef>

#define NV      25000
#define NE      100000
#define NE_PAD  100096
#define NODE_IN 74
#define EDGE_IN 12
#define DOUT    64
#define EHID    128
#define NSTEPS  6

// Scratch (device globals; no runtime allocation allowed)
__device__ float  d_h[NV * DOUT];
__device__ float  d_agg[NV * DOUT];
__device__ __half d_gh[NE_PAD * EHID];
__device__ __half d_We2t[DOUT * DOUT * EHID];         // We2^T [4096][128] fp16
__device__ __half d_ew[(size_t)NE * DOUT * DOUT];     // 819 MB

// ---------------------------------------------------------------------------
__global__ void k_project(const float* __restrict__ nf,
                          const float* __restrict__ Wp,
                          const float* __restrict__ bp) {
    int v = blockIdx.x;
    int o = threadIdx.x;
    __shared__ float row[NODE_IN];
    for (int i = o; i < NODE_IN; i += DOUT) row[i] = nf[v * NODE_IN + i];
    __syncthreads();
    float acc = bp[o];
#pragma unroll
    for (int i = 0; i < NODE_IN; i++) acc += row[i] * Wp[i * DOUT + o];
    d_h[v * DOUT + o] = fmaxf(acc, 0.f);
}

// ---------------------------------------------------------------------------
// 4 edges per 128-thread block: We1 column values reused across 4 edges.
// ---------------------------------------------------------------------------
__global__ void k_ehid(const float* __restrict__ ef,
                       const float* __restrict__ We1,
                       const float* __restrict__ be1) {
    int e0 = blockIdx.x * 4;
    int k  = threadIdx.x;
    __shared__ float rows[4][EDGE_IN];
    if (k < 4 * EDGE_IN) rows[k / EDGE_IN][k % EDGE_IN] = ef[e0 * EDGE_IN + k];
    __syncthreads();
    float b = be1[k];
    float a0 = b, a1 = b, a2 = b, a3 = b;
#pragma unroll
    for (int i = 0; i < EDGE_IN; i++) {
        float w = We1[i * EHID + k];
        a0 += rows[0][i] * w;
        a1 += rows[1][i] * w;
        a2 += rows[2][i] * w;
        a3 += rows[3][i] * w;
    }
    d_gh[(e0 + 0) * EHID + k] = __float2half(fmaxf(a0, 0.f));
    d_gh[(e0 + 1) * EHID + k] = __float2half(fmaxf(a1, 0.f));
    d_gh[(e0 + 2) * EHID + k] = __float2half(fmaxf(a2, 0.f));
    d_gh[(e0 + 3) * EHID + k] = __float2half(fmaxf(a3, 0.f));
}

// ---------------------------------------------------------------------------
__global__ void k_convW(const float* __restrict__ We2) {
    int idx = blockIdx.x * 256 + threadIdx.x;
    int n = idx >> 7, k = idx & 127;
    d_We2t[idx] = __float2half(We2[k * 4096 + n]);
}

// ---------------------------------------------------------------------------
// ew = g @ We2 + be2. HMMA m16n8k16, ldmatrix feeds, 64x64 warp tiles.
// Block tile 128 edges x 128 cols. K = 4 chunks of 32, THREE-stage cp.async
// ring (loads 3 chunks ahead; 5 syncthreads per CTA vs 8 in 2-stage).
// Dynamic smem 62 KB -> 3 CTAs/SM (regs 168 x 384 thr fits RF).
// ---------------------------------------------------------------------------
#define CH_STRIDE 40                       // halfs per row in chunk buffer (80B)
#define EW_STAGE_BYTES (2 * 128 * CH_STRIDE * 2)     // A+B per stage = 20480 B
#define EW_SMEM_BYTES  (3 * EW_STAGE_BYTES + 512)

__device__ __forceinline__ void cp16(uint32_t smem_dst, const void* gmem_src) {
    asm volatile("cp.async.cg.shared.global [%0], [%1], 16;\n"
                 :: "r"(smem_dst), "l"(gmem_src));
}

__global__ __launch_bounds__(128, 3) void k_ew(const float* __restrict__ be2) {
    extern __shared__ __align__(16) char smem[];
    __half* sb   = (__half*)smem;                       // 3 stages
    float*  be2s = (float*)(smem + 3 * EW_STAGE_BYTES);

    int tid  = threadIdx.x;
    int warp = tid >> 5, lane = tid & 31;
    int g = lane >> 2, tig = lane & 3;
    int wm = (warp >> 1) * 64;
    int wn = (warp & 1) * 64;
    int e0 = blockIdx.y * 128;
    int n0 = blockIdx.x * 128;

    be2s[tid] = be2[n0 + tid];

    uint32_t sbase;
    asm("{ .reg .u64 t; cvta.to.shared.u64 t, %1; cvt.u32.u64 %0, t; }"
        : "=r"(sbase) : "l"(smem));

    // async chunk loader: K cols [32kc, 32kc+32) into stage st
    auto load_chunk = [&](int kc, int st) {
        uint32_t stA = sbase + st * EW_STAGE_BYTES;
        uint32_t stB = stA + 128 * CH_STRIDE * 2;
#pragma unroll
        for (int it = 0; it < 4; it++) {
            int idx = tid + it * 128;              // 0..511
            int r = idx >> 2, j = idx & 3;
            cp16(stA + (r * CH_STRIDE + 8 * j) * 2,
                 &d_gh[(size_t)(e0 + r) * EHID + kc * 32 + 8 * j]);
            cp16(stB + (r * CH_STRIDE + 8 * j) * 2,
                 &d_We2t[(size_t)(n0 + r) * EHID + kc * 32 + 8 * j]);
        }
        asm volatile("cp.async.commit_group;\n");
    };

    load_chunk(0, 0);
    load_chunk(1, 1);
    load_chunk(2, 2);

    uint32_t offA[4], offB[4];
#pragma unroll
    for (int mt = 0; mt < 4; mt++)
        offA[mt] = (uint32_t)(((wm + mt * 16 + (lane & 15)) * CH_STRIDE +
                               (lane >> 4) * 8) * 2);
#pragma unroll
    for (int ntt = 0; ntt < 4; ntt++)
        offB[ntt] = (uint32_t)(128 * CH_STRIDE * 2 +
                               ((wn + ntt * 16 + ((lane >> 4) << 3) + (lane & 7)) *
                                CH_STRIDE + ((lane >> 3) & 1) * 8) * 2);

    float acc[4][8][4];
#pragma unroll
    for (int mt = 0; mt < 4; mt++)
#pragma unroll
        for (int nt = 0; nt < 8; nt++)
            acc[mt][nt][0] = acc[mt][nt][1] = acc[mt][nt][2] = acc[mt][nt][3] = 0.f;

#pragma unroll
    for (int kc = 0; kc < 4; kc++) {
        // groups committed so far: 3 (+1 after kc=0). need group kc complete.
        if (kc <= 1)      asm volatile("cp.async.wait_group 2;\n");
        else if (kc == 2) asm volatile("cp.async.wait_group 1;\n");
        else              asm volatile("cp.async.wait_group 0;\n");
        __syncthreads();

        int st = kc % 3;
        uint32_t base = sbase + st * EW_STAGE_BYTES;

#pragma unroll
        for (int kk = 0; kk < 2; kk++) {
            unsigned a[4][4];
#pragma unroll
            for (int mt = 0; mt < 4; mt++)
                asm volatile("ldmatrix.sync.aligned.m8n8.x4.shared.b16 {%0,%1,%2,%3}, [%4];"
                             : "=r"(a[mt][0]), "=r"(a[mt][1]), "=r"(a[mt][2]), "=r"(a[mt][3])
                             : "r"(base + offA[mt] + kk * 32));
#pragma unroll
            for (int ntt = 0; ntt < 4; ntt++) {
                unsigned b0, b1, b2, b3;
                asm volatile("ldmatrix.sync.aligned.m8n8.x4.shared.b16 {%0,%1,%2,%3}, [%4];"
                             : "=r"(b0), "=r"(b1), "=r"(b2), "=r"(b3)
                             : "r"(base + offB[ntt] + kk * 32));
#pragma unroll
                for (int mt = 0; mt < 4; mt++) {
                    asm volatile(
                        "mma.sync.aligned.m16n8k16.row.col.f32.f16.f16.f32 "
                        "{%0,%1,%2,%3}, {%4,%5,%6,%7}, {%8,%9}, {%0,%1,%2,%3};"
                        : "+f"(acc[mt][2*ntt][0]), "+f"(acc[mt][2*ntt][1]),
                          "+f"(acc[mt][2*ntt][2]), "+f"(acc[mt][2*ntt][3])
                        : "r"(a[mt][0]), "r"(a[mt][1]), "r"(a[mt][2]), "r"(a[mt][3]),
                          "r"(b0), "r"(b1));
                    asm volatile(
                        "mma.sync.aligned.m16n8k16.row.col.f32.f16.f16.f32 "
                        "{%0,%1,%2,%3}, {%4,%5,%6,%7}, {%8,%9}, {%0,%1,%2,%3};"
                        : "+f"(acc[mt][2*ntt+1][0]), "+f"(acc[mt][2*ntt+1][1]),
                          "+f"(acc[mt][2*ntt+1][2]), "+f"(acc[mt][2*ntt+1][3])
                        : "r"(a[mt][0]), "r"(a[mt][1]), "r"(a[mt][2]), "r"(a[mt][3]),
                          "r"(b2), "r"(b3));
                }
            }
        }
        if (kc == 0) {
            __syncthreads();               // all warps done reading stage 0
            load_chunk(3, 0);              // refill it with the last chunk
        }
    }
    __syncthreads();                       // all tile reads done; reuse smem

    __half(*Outs)[136] = reinterpret_cast<__half(*)[136]>(sb);   // 128x136
#pragma unroll
    for (int mt = 0; mt < 4; mt++)
#pragma unroll
        for (int nt = 0; nt < 8; nt++) {
            int r = wm + mt * 16 + g;
            int c = wn + nt * 8 + 2 * tig;
            __half2 v0 = __floats2half2_rn(acc[mt][nt][0] + be2s[c],
                                           acc[mt][nt][1] + be2s[c + 1]);
            __half2 v1 = __floats2half2_rn(acc[mt][nt][2] + be2s[c],
                                           acc[mt][nt][3] + be2s[c + 1]);
            *(__half2*)&Outs[r][c]     = v0;
            *(__half2*)&Outs[r + 8][c] = v1;
        }
    __syncthreads();

    for (int idx = tid; idx < 128 * 16; idx += 128) {
        int e = idx >> 4, j = idx & 15;
        if (e0 + e < NE)
            *(uint4*)&d_ew[(size_t)(e0 + e) * 4096 + n0 + 8 * j] =
                *(uint4*)&Outs[e][8 * j];
    }
}

// ---------------------------------------------------------------------------
// msg[e] = h[src[e]] @ ew[e]. Warp compaction + branch-free unroll-8 loop.
// ---------------------------------------------------------------------------
__global__ void k_msg(const int* __restrict__ src,
                      const int* __restrict__ dst) {
    int t  = threadIdx.x;
    int ty = threadIdx.y;
    int e  = blockIdx.x * 8 + ty;
    __shared__ float sval[8][64];
    __shared__ int   sidx[8][64];

    int s = src[e];
    float h0 = d_h[s * 64 + t];
    float h1 = d_h[s * 64 + 32 + t];
    unsigned m0 = __ballot_sync(0xffffffffu, h0 > 0.f);
    unsigned m1 = __ballot_sync(0xffffffffu, h1 > 0.f);
    int c0 = __popc(m0);
    if (h0 > 0.f) {
        int p = __popc(m0 & ((1u << t) - 1u));
        sval[ty][p] = h0; sidx[ty][p] = t;
    }
    if (h1 > 0.f) {
        int p = c0 + __popc(m1 & ((1u << t) - 1u));
        sval[ty][p] = h1; sidx[ty][p] = t + 32;
    }
    int nnz = c0 + __popc(m1);
    __syncwarp();

    const __half* ewp = d_ew + (size_t)e * 4096 + 2 * t;
    float ax = 0.f, ay = 0.f;
    int p = 0;
    for (; p + 8 <= nnz; p += 8) {
        int   iv[8];
        float hv[8];
        __half2 w[8];
#pragma unroll
        for (int u = 0; u < 8; u++) { iv[u] = sidx[ty][p + u]; hv[u] = sval[ty][p + u]; }
#pragma unroll
        for (int u = 0; u < 8; u++) w[u] = *(const __half2*)(ewp + iv[u] * 64);
#pragma unroll
        for (int u = 0; u < 8; u++) {
            float2 wf = __half22float2(w[u]);
            ax += hv[u] * wf.x;
            ay += hv[u] * wf.y;
        }
    }
    for (; p + 4 <= nnz; p += 4) {
        int   iv[4];
        float hv[4];
        __half2 w[4];
#pragma unroll
        for (int u = 0; u < 4; u++) { iv[u] = sidx[ty][p + u]; hv[u] = sval[ty][p + u]; }
#pragma unroll
        for (int u = 0; u < 4; u++) w[u] = *(const __half2*)(ewp + iv[u] * 64);
#pragma unroll
        for (int u = 0; u < 4; u++) {
            float2 wf = __half22float2(w[u]);
            ax += hv[u] * wf.x;
            ay += hv[u] * wf.y;
        }
    }
    for (; p < nnz; p++) {
        int   i  = sidx[ty][p];
        float hv = sval[ty][p];
        __half2 w = *(const __half2*)(ewp + i * 64);
        float2 wf = __half22float2(w);
        ax += hv * wf.x;
        ay += hv * wf.y;
    }
    int dv = dst[e];
    atomicAdd(&d_agg[dv * 64 + 2 * t],     ax);
    atomicAdd(&d_agg[dv * 64 + 2 * t + 1], ay);
}

// ---------------------------------------------------------------------------
__global__ void k_zero() {
    int i = blockIdx.x * blockDim.x + threadIdx.x;
    if (i < NV * DOUT) d_agg[i] = 0.f;
}

__global__ void k_relu(const float* __restrict__ bias, float* __restrict__ out) {
    int idx = blockIdx.x * blockDim.x + threadIdx.x;
    int i = idx * 4;
    if (i < NV * DOUT) {
        float4 a = *(float4*)&d_agg[i];
        float4 b = *(const float4*)&bias[i & (DOUT - 1)];
        float4 v;
        v.x = fmaxf(a.x + b.x, 0.f);
        v.y = fmaxf(a.y + b.y, 0.f);
        v.z = fmaxf(a.z + b.z, 0.f);
        v.w = fmaxf(a.w + b.w, 0.f);
        *(float4*)&d_agg[i] = make_float4(0.f, 0.f, 0.f, 0.f);
        *(float4*)&d_h[i] = v;
        if (out) *(float4*)&out[i] = v;
    }
}

// ---------------------------------------------------------------------------
extern "C" void kernel_launch(void* const* d_in, const int* in_sizes, int n_in,
                              void* d_out, int out_size) {
    const float* nf   = (const float*)d_in[0];
    const float* ef   = (const float*)d_in[1];
    const int*   src  = (const int*)  d_in[2];
    const int*   dst  = (const int*)  d_in[3];
    const float* Wp   = (const float*)d_in[4];
    const float* bp   = (const float*)d_in[5];
    const float* We1  = (const float*)d_in[6];
    const float* be1  = (const float*)d_in[7];
    const float* We2  = (const float*)d_in[8];
    const float* be2  = (const float*)d_in[9];
    const float* bias = (const float*)d_in[10];
    float* out = (float*)d_out;

    cudaFuncSetAttribute(k_ew, cudaFuncAttributeMaxDynamicSharedMemorySize,
                         EW_SMEM_BYTES);

    k_project<<<NV, DOUT>>>(nf, Wp, bp);
    k_ehid<<<NE / 4, EHID>>>(ef, We1, be1);
    k_convW<<<(DOUT * DOUT * EHID) / 256, 256>>>(We2);
    k_ew<<<dim3(32, 782), 128, EW_SMEM_BYTES>>>(be2);

    k_zero<<<(NV * DOUT) / 256, 256>>>();
    for (int s = 0; s < NSTEPS; s++) {
        k_msg<<<NE / 8, dim3(32, 8)>>>(src, dst);
        k_relu<<<(NV * DOUT / 4 + 255) / 256, 256>>>(bias, (s == NSTEPS - 1) ? out : nullptr);
    }
}